// round 15
// baseline (speedup 1.0000x reference)
#include <cuda_runtime.h>
#include <cstdint>

#define BB 64
#define NN 1024

// Output layout (flattened reference tuple, all float32):
#define OFF_DONE 0
#define OFF_NM   1
#define OFF_ADJ  (1 + BB*NN)
#define OFF_FA   (OFF_ADJ + (size_t)BB*NN*NN)
#define OFF_PT   (OFF_FA + BB)
#define OFF_STEP (OFF_PT + BB)

__device__ float g_fp[BB * NN];     // fpresent[b, i]
__device__ float g_dlast[NN];       // dist[:, N-1]
__device__ float g_nmlast[BB];      // new_mask[b, N-1]
__device__ float g_op[BB * NN];     // SoA copies of inputs (for aligned loads)
__device__ float g_cl[BB * NN];
__device__ float g_du[BB * NN];

__global__ void k_prep(const float* __restrict__ inputs,
                       const float* __restrict__ dist,
                       const float* __restrict__ mask,
                       const float* __restrict__ ptime,
                       const int*   __restrict__ pres,
                       const int*   __restrict__ fut,
                       float* out)
{
    int b = blockIdx.x;
    int j = threadIdx.x;

    int   pa = pres[b];
    float pt = ptime[b];

    float4 in4 = *reinterpret_cast<const float4*>(inputs + ((size_t)(b * NN + j)) * 4);
    float op = in4.x, cl = in4.y, dur = in4.z;
    float T0 = inputs[3];

    float dlast  = dist[(size_t)j * NN + (NN - 1)];
    float arrive = dist[(size_t)pa * NN + j] + pt;
    float wait   = fmaxf(0.0f, op - arrive);
    float t      = arrive + wait;

    bool c1 = t <= cl;
    bool c2 = ((t + dur) + dlast) <= T0;

    float m = mask[b * NN + j];
    if (j == pa) m = 0.0f;
    float nm = (c1 && c2) ? m : 0.0f;

    float fpres = t + dur;

    out[OFF_NM + b * NN + j] = nm;
    g_fp[b * NN + j] = fpres;
    g_op[b * NN + j] = op;
    g_cl[b * NN + j] = cl;
    g_du[b * NN + j] = dur;
    if (b == 0) g_dlast[j] = dlast;
    if (j == NN - 1) g_nmlast[b] = nm;

    int fb = fut[b];
    if (j == fb) out[OFF_PT + b] = fpres;
    if (j == 0) {
        out[OFF_FA + b]   = (float)fb;
        out[OFF_STEP + b] = 1.0f;
    }
}

// Assemble x[jb..jb+3] (jb = j4+3) from own aligned float4 a = [j4..j4+3] and
// the next lane's values via shfl; lane 31 substitutes its extra load bx.
__device__ __forceinline__ void shift3(float4 a, float4 bx, bool haveB, float o[4])
{
    o[0] = a.w;
    o[1] = __shfl_down_sync(0xffffffffu, a.x, 1);
    o[2] = __shfl_down_sync(0xffffffffu, a.y, 1);
    o[3] = __shfl_down_sync(0xffffffffu, a.z, 1);
    if (haveB) { o[1] = bx.x; o[2] = bx.y; o[3] = bx.z; }
}

// adj kernel — R13's shfl-aligned interior unchanged; tiling RR=16/BT=4
// (grid 1024): halves the dist L2 re-read vs R13 while keeping ~7 blocks/SM
// of parallelism (R14 showed grid 512 starves this interior).
#define BT 4
#define RR 16

__global__ __launch_bounds__(256) void k_adj(const float* __restrict__ inputs,
                                             const float* __restrict__ dist,
                                             float* out)
{
    const int ITILES = NN / RR;                 // 64
    int itile = blockIdx.x & (ITILES - 1);
    int b0    = (blockIdx.x / ITILES) * BT;
    int i0    = itile * RR;
    int tid   = threadIdx.x;
    int warp  = tid >> 5;
    int lane  = tid & 31;
    int jw    = warp << 7;
    int j4    = jw + 4 * lane;                  // aligned load base
    int jb    = j4 + 3;                         // aligned store base

    bool tail  = (warp == 7 && lane == 31);     // stores only scalar j=1023
    bool haveB = (lane == 31) && (warp < 7);    // needs next-chunk float4

    if (blockIdx.x == 0 && tid == 0) {
        float any = 0.0f;
#pragma unroll
        for (int b = 0; b < BB; b++) any = fmaxf(any, g_nmlast[b]);
        out[OFF_DONE] = (any > 0.0f) ? 0.0f : 1.0f;
    }

    float dl[4];
#pragma unroll
    for (int e = 0; e < 4; e++) dl[e] = g_dlast[min(jb + e, NN - 1)];

    const float4 zf4 = make_float4(0.f, 0.f, 0.f, 0.f);

    for (int bb = 0; bb < BT; bb++) {
        int b = b0 + bb;
        const float* opb = g_op + b * NN;
        const float* clb = g_cl + b * NN;
        const float* dub = g_du + b * NN;

        float4 aop = *reinterpret_cast<const float4*>(opb + j4);
        float4 acl = *reinterpret_cast<const float4*>(clb + j4);
        float4 adu = *reinterpret_cast<const float4*>(dub + j4);
        float4 bop = zf4, bcl = zf4, bdu = zf4;
        if (haveB) {
            bop = *reinterpret_cast<const float4*>(opb + jw + 128);
            bcl = *reinterpret_cast<const float4*>(clb + jw + 128);
            bdu = *reinterpret_cast<const float4*>(dub + jw + 128);
        }
        float op[4], cl[4], du[4];
        shift3(aop, bop, haveB, op);
        shift3(acl, bcl, haveB, cl);
        shift3(adu, bdu, haveB, du);

        float4 nm4 = *reinterpret_cast<const float4*>(out + OFF_NM + b * NN + jb);
        float nm[4] = {nm4.x, nm4.y, nm4.z, nm4.w};

        float Tb = inputs[((size_t)b * NN) * 4 + 3];

#pragma unroll
        for (int r = 0; r < RR; r++) {
            int   i  = i0 + r;
            float fp = g_fp[b * NN + i];
            const float* drow = dist + (size_t)i * NN;
            float* orow = out + OFF_ADJ + ((size_t)(b * NN + i)) * NN;

            float4 ad = *reinterpret_cast<const float4*>(drow + j4);
            float4 bd = zf4;
            if (haveB) bd = *reinterpret_cast<const float4*>(drow + jw + 128);
            float d[4];
            shift3(ad, bd, haveB, d);

            float v[4];
#pragma unroll
            for (int e = 0; e < 4; e++) {
                float arr2 = d[e] + fp;
                float w    = fmaxf(0.0f, op[e] - arr2);
                float s    = arr2 + w;
                bool a1 = s <= cl[e];
                bool a2 = ((s + du[e]) + dl[e]) <= Tb;
                float x = (a1 && a2) ? nm[e] : 0.0f;
                if (jb + e == i) x = 1.0f;
                v[e] = x;
            }
            if (!tail)
                *reinterpret_cast<float4*>(orow + jb) =
                    make_float4(v[0], v[1], v[2], v[3]);
            else
                orow[NN - 1] = v[0];
        }
    }

    // Leftover columns j in {0, 1, 2}
    if (tid < 3) {
        int j = tid;
        float dlL = g_dlast[j];
        for (int bb = 0; bb < BT; bb++) {
            int b = b0 + bb;
            float opL = g_op[b * NN + j];
            float clL = g_cl[b * NN + j];
            float duL = g_du[b * NN + j];
            float nmL = out[OFF_NM + b * NN + j];
            float Tb  = inputs[((size_t)b * NN) * 4 + 3];
#pragma unroll
            for (int r = 0; r < RR; r++) {
                int i = i0 + r;
                float fp = g_fp[b * NN + i];
                float arr2 = dist[(size_t)i * NN + j] + fp;
                float w    = fmaxf(0.0f, opL - arr2);
                float s    = arr2 + w;
                bool a1 = s <= clL;
                bool a2 = ((s + duL) + dlL) <= Tb;
                float x = (a1 && a2) ? nmL : 0.0f;
                if (j == i) x = 1.0f;
                out[OFF_ADJ + ((size_t)(b * NN + i)) * NN + j] = x;
            }
        }
    }
}

extern "C" void kernel_launch(void* const* d_in, const int* in_sizes, int n_in,
                              void* d_out, int out_size)
{
    const float* inputs = (const float*)d_in[0];   // (B, N, 4) f32
    const float* dist   = (const float*)d_in[1];   // (N, N)   f32
    const float* mask   = (const float*)d_in[2];   // (B, N)   f32
    const float* ptime  = (const float*)d_in[3];   // (B, 1)   f32
    const int*   pres   = (const int*)d_in[4];     // (B,)     i32
    const int*   fut    = (const int*)d_in[5];     // (B,)     i32
    float* out = (float*)d_out;

    k_prep<<<BB, NN>>>(inputs, dist, mask, ptime, pres, fut, out);
    k_adj<<<(NN / RR) * (BB / BT), 256>>>(inputs, dist, out);
}

// round 16
// speedup vs baseline: 1.1541x; 1.1541x over previous
#include <cuda_runtime.h>
#include <cstdint>

#define BB 64
#define NN 1024

// Output layout (flattened reference tuple, all float32):
#define OFF_DONE 0
#define OFF_NM   1
#define OFF_ADJ  (1 + BB*NN)
#define OFF_FA   (OFF_ADJ + (size_t)BB*NN*NN)
#define OFF_PT   (OFF_FA + BB)
#define OFF_STEP (OFF_PT + BB)

__device__ float g_fp[BB * NN];     // fpresent[b, i]
__device__ float g_dlast[NN];       // dist[:, N-1]
__device__ float g_nmlast[BB];      // new_mask[b, N-1]
__device__ float g_op[BB * NN];     // SoA copies of inputs (for aligned loads)
__device__ float g_cl[BB * NN];
__device__ float g_du[BB * NN];

__global__ void k_prep(const float* __restrict__ inputs,
                       const float* __restrict__ dist,
                       const float* __restrict__ mask,
                       const float* __restrict__ ptime,
                       const int*   __restrict__ pres,
                       const int*   __restrict__ fut,
                       float* out)
{
    int b = blockIdx.x;
    int j = threadIdx.x;

    int   pa = pres[b];
    float pt = ptime[b];

    float4 in4 = *reinterpret_cast<const float4*>(inputs + ((size_t)(b * NN + j)) * 4);
    float op = in4.x, cl = in4.y, dur = in4.z;
    float T0 = inputs[3];

    float dlast  = dist[(size_t)j * NN + (NN - 1)];
    float arrive = dist[(size_t)pa * NN + j] + pt;
    float wait   = fmaxf(0.0f, op - arrive);
    float t      = arrive + wait;

    bool c1 = t <= cl;
    bool c2 = ((t + dur) + dlast) <= T0;

    float m = mask[b * NN + j];
    if (j == pa) m = 0.0f;
    float nm = (c1 && c2) ? m : 0.0f;

    float fpres = t + dur;

    out[OFF_NM + b * NN + j] = nm;
    g_fp[b * NN + j] = fpres;
    g_op[b * NN + j] = op;
    g_cl[b * NN + j] = cl;
    g_du[b * NN + j] = dur;
    if (b == 0) g_dlast[j] = dlast;
    if (j == NN - 1) g_nmlast[b] = nm;

    int fb = fut[b];
    if (j == fb) out[OFF_PT + b] = fpres;
    if (j == 0) {
        out[OFF_FA + b]   = (float)fb;
        out[OFF_STEP + b] = 1.0f;
    }
}

// Assemble x[jb..jb+3] (jb = j4+3) from own aligned float4 a = [j4..j4+3] and
// the next lane's values via shfl; lane 31 substitutes its extra load bx.
__device__ __forceinline__ void shift3(float4 a, float4 bx, bool haveB, float o[4])
{
    o[0] = a.w;
    o[1] = __shfl_down_sync(0xffffffffu, a.x, 1);
    o[2] = __shfl_down_sync(0xffffffffu, a.y, 1);
    o[3] = __shfl_down_sync(0xffffffffu, a.z, 1);
    if (haveB) { o[1] = bx.x; o[2] = bx.y; o[3] = bx.z; }
}

// adj kernel — R13 champion (BT=4/RR=8/grid 2048, shfl-aligned interior),
// with PAIRWISE row processing: both rows' dist LDG.128 issued back-to-back
// before either row's compute/store (doubles per-thread outstanding loads at
// the one latency-exposed point; ~6 extra regs, no structural change).
#define BT 4
#define RR 8

__global__ __launch_bounds__(256) void k_adj(const float* __restrict__ inputs,
                                             const float* __restrict__ dist,
                                             float* out)
{
    const int ITILES = NN / RR;                 // 128
    int itile = blockIdx.x & (ITILES - 1);
    int b0    = (blockIdx.x / ITILES) * BT;
    int i0    = itile * RR;
    int tid   = threadIdx.x;
    int warp  = tid >> 5;
    int lane  = tid & 31;
    int jw    = warp << 7;
    int j4    = jw + 4 * lane;                  // aligned load base
    int jb    = j4 + 3;                         // aligned store base

    bool tail  = (warp == 7 && lane == 31);     // stores only scalar j=1023
    bool haveB = (lane == 31) && (warp < 7);    // needs next-chunk float4

    if (blockIdx.x == 0 && tid == 0) {
        float any = 0.0f;
#pragma unroll
        for (int b = 0; b < BB; b++) any = fmaxf(any, g_nmlast[b]);
        out[OFF_DONE] = (any > 0.0f) ? 0.0f : 1.0f;
    }

    float dl[4];
#pragma unroll
    for (int e = 0; e < 4; e++) dl[e] = g_dlast[min(jb + e, NN - 1)];

    const float4 zf4 = make_float4(0.f, 0.f, 0.f, 0.f);

    for (int bb = 0; bb < BT; bb++) {
        int b = b0 + bb;
        const float* opb = g_op + b * NN;
        const float* clb = g_cl + b * NN;
        const float* dub = g_du + b * NN;

        float4 aop = *reinterpret_cast<const float4*>(opb + j4);
        float4 acl = *reinterpret_cast<const float4*>(clb + j4);
        float4 adu = *reinterpret_cast<const float4*>(dub + j4);
        float4 bop = zf4, bcl = zf4, bdu = zf4;
        if (haveB) {
            bop = *reinterpret_cast<const float4*>(opb + jw + 128);
            bcl = *reinterpret_cast<const float4*>(clb + jw + 128);
            bdu = *reinterpret_cast<const float4*>(dub + jw + 128);
        }
        float op[4], cl[4], du[4];
        shift3(aop, bop, haveB, op);
        shift3(acl, bcl, haveB, cl);
        shift3(adu, bdu, haveB, du);

        float4 nm4 = *reinterpret_cast<const float4*>(out + OFF_NM + b * NN + jb);
        float nm[4] = {nm4.x, nm4.y, nm4.z, nm4.w};

        float Tb = inputs[((size_t)b * NN) * 4 + 3];

#pragma unroll
        for (int r = 0; r < RR; r += 2) {
            int i_0 = i0 + r, i_1 = i0 + r + 1;
            const float* drow0 = dist + (size_t)i_0 * NN;
            const float* drow1 = dist + (size_t)i_1 * NN;

            // front-batched: both rows' loads before any compute
            float4 ad0 = *reinterpret_cast<const float4*>(drow0 + j4);
            float4 ad1 = *reinterpret_cast<const float4*>(drow1 + j4);
            float4 bd0 = zf4, bd1 = zf4;
            if (haveB) {
                bd0 = *reinterpret_cast<const float4*>(drow0 + jw + 128);
                bd1 = *reinterpret_cast<const float4*>(drow1 + jw + 128);
            }
            float fp0 = g_fp[b * NN + i_0];
            float fp1 = g_fp[b * NN + i_1];

            float d0[4], d1[4];
            shift3(ad0, bd0, haveB, d0);
            shift3(ad1, bd1, haveB, d1);

            float* orow0 = out + OFF_ADJ + ((size_t)(b * NN + i_0)) * NN;
            float* orow1 = out + OFF_ADJ + ((size_t)(b * NN + i_1)) * NN;

            float v0[4], v1[4];
#pragma unroll
            for (int e = 0; e < 4; e++) {
                {
                    float arr2 = d0[e] + fp0;
                    float w    = fmaxf(0.0f, op[e] - arr2);
                    float s    = arr2 + w;
                    bool a1 = s <= cl[e];
                    bool a2 = ((s + du[e]) + dl[e]) <= Tb;
                    float x = (a1 && a2) ? nm[e] : 0.0f;
                    if (jb + e == i_0) x = 1.0f;
                    v0[e] = x;
                }
                {
                    float arr2 = d1[e] + fp1;
                    float w    = fmaxf(0.0f, op[e] - arr2);
                    float s    = arr2 + w;
                    bool a1 = s <= cl[e];
                    bool a2 = ((s + du[e]) + dl[e]) <= Tb;
                    float x = (a1 && a2) ? nm[e] : 0.0f;
                    if (jb + e == i_1) x = 1.0f;
                    v1[e] = x;
                }
            }
            if (!tail) {
                *reinterpret_cast<float4*>(orow0 + jb) =
                    make_float4(v0[0], v0[1], v0[2], v0[3]);
                *reinterpret_cast<float4*>(orow1 + jb) =
                    make_float4(v1[0], v1[1], v1[2], v1[3]);
            } else {
                orow0[NN - 1] = v0[0];
                orow1[NN - 1] = v1[0];
            }
        }
    }

    // Leftover columns j in {0, 1, 2}
    if (tid < 3) {
        int j = tid;
        float dlL = g_dlast[j];
        for (int bb = 0; bb < BT; bb++) {
            int b = b0 + bb;
            float opL = g_op[b * NN + j];
            float clL = g_cl[b * NN + j];
            float duL = g_du[b * NN + j];
            float nmL = out[OFF_NM + b * NN + j];
            float Tb  = inputs[((size_t)b * NN) * 4 + 3];
#pragma unroll
            for (int r = 0; r < RR; r++) {
                int i = i0 + r;
                float fp = g_fp[b * NN + i];
                float arr2 = dist[(size_t)i * NN + j] + fp;
                float w    = fmaxf(0.0f, opL - arr2);
                float s    = arr2 + w;
                bool a1 = s <= clL;
                bool a2 = ((s + duL) + dlL) <= Tb;
                float x = (a1 && a2) ? nmL : 0.0f;
                if (j == i) x = 1.0f;
                out[OFF_ADJ + ((size_t)(b * NN + i)) * NN + j] = x;
            }
        }
    }
}

extern "C" void kernel_launch(void* const* d_in, const int* in_sizes, int n_in,
                              void* d_out, int out_size)
{
    const float* inputs = (const float*)d_in[0];   // (B, N, 4) f32
    const float* dist   = (const float*)d_in[1];   // (N, N)   f32
    const float* mask   = (const float*)d_in[2];   // (B, N)   f32
    const float* ptime  = (const float*)d_in[3];   // (B, 1)   f32
    const int*   pres   = (const int*)d_in[4];     // (B,)     i32
    const int*   fut    = (const int*)d_in[5];     // (B,)     i32
    float* out = (float*)d_out;

    k_prep<<<BB, NN>>>(inputs, dist, mask, ptime, pres, fut, out);
    k_adj<<<(NN / RR) * (BB / BT), 256>>>(inputs, dist, out);
}